// round 10
// baseline (speedup 1.0000x reference)
#include <cuda_runtime.h>
#include <cuda_bf16.h>
#include <cstdint>

#define B 16
#define S 200
#define D 256
#define H 8
#define W 32
#define RS 0.17677669529663689f   // 1/sqrt(32)

// ---------------- scratch (no allocations allowed) ----------------
__device__ float g_q[B * S * D];
__device__ float g_k[B * S * D];
__device__ float g_v[B * S * D];

// ---------------- tf32 helpers ----------------
__device__ __forceinline__ uint32_t tf32_hi_bits(float a) {
    return __float_as_uint(a) & 0xffffe000u;
}

__device__ __forceinline__ void mma_tf32(
    float& c0, float& c1, float& c2, float& c3,
    uint32_t a0, uint32_t a1, uint32_t a2, uint32_t a3,
    uint32_t b0, uint32_t b1)
{
    asm volatile(
        "mma.sync.aligned.m16n8k8.row.col.f32.tf32.tf32.f32 "
        "{%0,%1,%2,%3}, {%4,%5,%6,%7}, {%8,%9}, {%0,%1,%2,%3};"
        : "+f"(c0), "+f"(c1), "+f"(c2), "+f"(c3)
        : "r"(a0), "r"(a1), "r"(a2), "r"(a3), "r"(b0), "r"(b1));
}

// ---------------- cp.async helpers (proj only) ----------------
__device__ __forceinline__ void cp_async16(uint32_t dst, const void* src) {
    asm volatile("cp.async.cg.shared.global [%0], [%1], 16;" :: "r"(dst), "l"(src));
}
#define CP_COMMIT() asm volatile("cp.async.commit_group;" ::: "memory")
#define CP_WAIT1()  asm volatile("cp.async.wait_group 1;" ::: "memory")

// ---------------- kernel 1: tf32 TC projection, single-wave config ----------------
// 64x64 tile, 128 threads (4 warps in 2x2), 600 blocks, 6 blocks/SM -> ONE wave.
#define PTM 64
#define PTN 64
#define PTK 32
#define PPAD 4
#define PLD (PTK + PPAD)

__global__ __launch_bounds__(128) void proj_tc_kernel(
    const float* __restrict__ x,
    const float* __restrict__ Wq, const float* __restrict__ bq,
    const float* __restrict__ Wk, const float* __restrict__ bk,
    const float* __restrict__ Wv, const float* __restrict__ bv)
{
    __shared__ float sa[2][PTM][PLD];   // x tiles, 18.4 KB
    __shared__ float sb[2][PTN][PLD];   // W tiles, 18.4 KB

    const int tid  = threadIdx.x;
    const int lane = tid & 31;
    const int wid  = tid >> 5;                    // 0..3
    const int m0   = blockIdx.x * PTM;
    const int mat  = blockIdx.y >> 2;             // 0=q,1=k,2=v
    const int nc0  = (blockIdx.y & 3) * PTN;

    const float* Wm   = (mat == 0) ? Wq : (mat == 1) ? Wk : Wv;
    const float* bias = (mat == 0) ? bq : (mat == 1) ? bk : bv;
    float* dst        = (mat == 0) ? g_q : (mat == 1) ? g_k : g_v;

    const int warp_m = wid & 1;      // 2 warps over M (32 rows each)
    const int warp_n = wid >> 1;     // 2 warps over N (32 cols each)
    const int wm0 = warp_m * 32;
    const int wn0 = warp_n * 32;

    const int g  = lane >> 2;
    const int tg = lane & 3;

    // load mapping: 128 threads x 16 floats = 64x32 tile
    const int lrow = tid >> 1;           // 0..63
    const int lk   = (tid & 1) * 16;     // 0 or 16

    const float* xsrc = x  + (size_t)(m0  + lrow) * D + lk;
    const float* wsrc = Wm + (size_t)(nc0 + lrow) * D + lk;
    uint32_t sa_dst = (uint32_t)__cvta_generic_to_shared(&sa[0][lrow][lk]);
    uint32_t sb_dst = (uint32_t)__cvta_generic_to_shared(&sb[0][lrow][lk]);
    const uint32_t bufstride = (uint32_t)(PTM * PLD * 4);

    #define PROJ_PREFETCH(t, s)                                            \
        do {                                                               \
            cp_async16(sa_dst + (s) * bufstride,      xsrc + (t) * PTK);       \
            cp_async16(sa_dst + (s) * bufstride + 16, xsrc + (t) * PTK + 4);   \
            cp_async16(sa_dst + (s) * bufstride + 32, xsrc + (t) * PTK + 8);   \
            cp_async16(sa_dst + (s) * bufstride + 48, xsrc + (t) * PTK + 12);  \
            cp_async16(sb_dst + (s) * bufstride,      wsrc + (t) * PTK);       \
            cp_async16(sb_dst + (s) * bufstride + 16, wsrc + (t) * PTK + 4);   \
            cp_async16(sb_dst + (s) * bufstride + 32, wsrc + (t) * PTK + 8);   \
            cp_async16(sb_dst + (s) * bufstride + 48, wsrc + (t) * PTK + 12);  \
            CP_COMMIT();                                                   \
        } while (0)

    float c[2][4][4];
    #pragma unroll
    for (int i = 0; i < 2; i++)
        #pragma unroll
        for (int j = 0; j < 4; j++)
            #pragma unroll
            for (int r = 0; r < 4; r++) c[i][j][r] = 0.f;

    PROJ_PREFETCH(0, 0);

    #pragma unroll 1
    for (int t = 0; t < D / PTK; t++) {
        if (t + 1 < D / PTK) PROJ_PREFETCH(t + 1, (t + 1) & 1);
        else                 CP_COMMIT();
        CP_WAIT1();
        __syncthreads();

        const int s = t & 1;
        #pragma unroll
        for (int kk = 0; kk < 4; kk++) {
            const int kc = kk * 8;
            float af[2][4];
            #pragma unroll
            for (int i = 0; i < 2; i++) {
                const int rb = wm0 + 16 * i + g;
                af[i][0] = sa[s][rb    ][kc + tg];
                af[i][1] = sa[s][rb + 8][kc + tg];
                af[i][2] = sa[s][rb    ][kc + tg + 4];
                af[i][3] = sa[s][rb + 8][kc + tg + 4];
            }
            float bf[4][2];
            #pragma unroll
            for (int j = 0; j < 4; j++) {
                const int cb = wn0 + 8 * j + g;
                bf[j][0] = sb[s][cb][kc + tg];
                bf[j][1] = sb[s][cb][kc + tg + 4];
            }
            uint32_t ah[2][4], al[2][4], bh[4][2], bl[4][2];
            #pragma unroll
            for (int i = 0; i < 2; i++)
                #pragma unroll
                for (int r = 0; r < 4; r++) {
                    uint32_t hb = tf32_hi_bits(af[i][r]);
                    ah[i][r] = hb;
                    float lo = af[i][r] - __uint_as_float(hb);
                    al[i][r] = tf32_hi_bits(lo);
                }
            #pragma unroll
            for (int j = 0; j < 4; j++)
                #pragma unroll
                for (int r = 0; r < 2; r++) {
                    uint32_t hb = tf32_hi_bits(bf[j][r]);
                    bh[j][r] = hb;
                    float lo = bf[j][r] - __uint_as_float(hb);
                    bl[j][r] = tf32_hi_bits(lo);
                }
            #pragma unroll
            for (int i = 0; i < 2; i++)
                #pragma unroll
                for (int j = 0; j < 4; j++) {
                    mma_tf32(c[i][j][0], c[i][j][1], c[i][j][2], c[i][j][3],
                             ah[i][0], ah[i][1], ah[i][2], ah[i][3],
                             bh[j][0], bh[j][1]);
                    mma_tf32(c[i][j][0], c[i][j][1], c[i][j][2], c[i][j][3],
                             al[i][0], al[i][1], al[i][2], al[i][3],
                             bh[j][0], bh[j][1]);
                    mma_tf32(c[i][j][0], c[i][j][1], c[i][j][2], c[i][j][3],
                             ah[i][0], ah[i][1], ah[i][2], ah[i][3],
                             bl[j][0], bl[j][1]);
                }
        }
        __syncthreads();
    }

    #pragma unroll
    for (int i = 0; i < 2; i++) {
        const int r0 = m0 + wm0 + 16 * i + g;
        #pragma unroll
        for (int j = 0; j < 4; j++) {
            const int cg = nc0 + wn0 + 8 * j + tg * 2;
            const float b0v = bias[cg], b1v = bias[cg + 1];
            float2 v0 = make_float2(c[i][j][0] + b0v, c[i][j][1] + b1v);
            float2 v1 = make_float2(c[i][j][2] + b0v, c[i][j][3] + b1v);
            *(float2*)&dst[(size_t)r0 * D + cg]       = v0;
            *(float2*)&dst[(size_t)(r0 + 8) * D + cg] = v1;
        }
    }
}

// ---------------- kernel 2: fused attention, 128 threads/block (best known) ----------------
__global__ __launch_bounds__(128, 12) void fused_attn_kernel(
    const float* __restrict__ tK, const float* __restrict__ tV,
    const int* __restrict__ mask, float* __restrict__ out)
{
    __shared__ float sp[H][S];          // 6.4 KB
    __shared__ float4 pbuf[2][64];      // 2 KB

    const int bi = blockIdx.x;
    const int b  = bi / S;
    const int warp = threadIdx.x >> 5;  // 0..3
    const int lane = threadIdx.x & 31;

    // ---- Phase A ----
    {
        const float* qrow = g_q + (size_t)bi * D + lane * 8;
        const float4 qa = *(const float4*)(qrow);
        const float4 qb = *(const float4*)(qrow + 4);

        #pragma unroll 5
        for (int j = warp; j < S; j += 4) {
            const float* tp = tK  + ((size_t)bi * S + j) * D + lane * 8;
            const float* kp = g_k + ((size_t)(b * S + j)) * D + lane * 8;
            float4 t0 = __ldcs((const float4*)(tp));
            float4 t1 = __ldcs((const float4*)(tp + 4));
            float4 k0 = *(const float4*)(kp);
            float4 k1 = *(const float4*)(kp + 4);

            float p = qa.x * (t0.x + k0.x) + qa.y * (t0.y + k0.y)
                    + qa.z * (t0.z + k0.z) + qa.w * (t0.w + k0.w)
                    + qb.x * (t1.x + k1.x) + qb.y * (t1.y + k1.y)
                    + qb.z * (t1.z + k1.z) + qb.w * (t1.w + k1.w);

            p += __shfl_xor_sync(0xFFFFFFFFu, p, 1);
            p += __shfl_xor_sync(0xFFFFFFFFu, p, 2);
            if ((lane & 3) == 0) sp[lane >> 2][j] = p;
        }
    }
    __syncthreads();

    // ---- Phase B: warp handles heads warp and warp+4 ----
    #pragma unroll
    for (int hh = 0; hh < 2; hh++) {
        const int h = warp + hh * 4;
        float vals[7];
        float mx = -1e30f;
        #pragma unroll
        for (int t = 0; t < 7; t++) {
            int j = lane + t * 32;
            if (j < S) {
                float mb = 10000.0f * (1.0f - (float)mask[b * S + j]);
                vals[t] = sp[h][j] * RS + mb;
            } else {
                vals[t] = -1e30f;
            }
            mx = fmaxf(mx, vals[t]);
        }
        #pragma unroll
        for (int o = 16; o; o >>= 1) mx = fmaxf(mx, __shfl_xor_sync(0xFFFFFFFFu, mx, o));

        float sum = 0.f;
        #pragma unroll
        for (int t = 0; t < 7; t++) {
            vals[t] = __expf(vals[t] - mx);
            sum += vals[t];
        }
        #pragma unroll
        for (int o = 16; o; o >>= 1) sum += __shfl_xor_sync(0xFFFFFFFFu, sum, o);

        const float inv = 1.0f / sum;
        #pragma unroll
        for (int t = 0; t < 7; t++) {
            int j = lane + t * 32;
            if (j < S) sp[h][j] = vals[t] * inv;
        }
    }
    __syncthreads();

    // ---- Phase C ----
    {
        const int g = threadIdx.x >> 6;     // j-group 0..1
        const int l = threadIdx.x & 63;     // d-slice 0..63
        const int d = l * 4;
        const int h = l >> 3;

        const float* tvb = tV  + ((size_t)bi * S) * D + d;
        const float* vvb = g_v + ((size_t)b * S) * D + d;

        float4 acc = make_float4(0.f, 0.f, 0.f, 0.f);
        #pragma unroll 5
        for (int j = g; j < S; j += 2) {
            float4 tv = __ldcs((const float4*)(tvb + (size_t)j * D));
            float4 vv = *(const float4*)(vvb + (size_t)j * D);
            float pj = sp[h][j];
            acc.x += pj * (tv.x + vv.x);
            acc.y += pj * (tv.y + vv.y);
            acc.z += pj * (tv.z + vv.z);
            acc.w += pj * (tv.w + vv.w);
        }
        pbuf[g][l] = acc;
    }
    __syncthreads();

    if (threadIdx.x < 64) {
        const int l = threadIdx.x;
        float4 a0 = pbuf[0][l], a1 = pbuf[1][l];
        float4 r;
        r.x = a0.x + a1.x;
        r.y = a0.y + a1.y;
        r.z = a0.z + a1.z;
        r.w = a0.w + a1.w;
        *(float4*)(out + (size_t)bi * D + l * 4) = r;
    }
}

// ---------------- launch ----------------
extern "C" void kernel_launch(void* const* d_in, const int* in_sizes, int n_in,
                              void* d_out, int out_size)
{
    const float* x    = (const float*)d_in[0];
    const float* tK   = (const float*)d_in[1];
    const float* tV   = (const float*)d_in[2];
    const int*   mask = (const int*)  d_in[3];
    const float* Wq   = (const float*)d_in[4];
    const float* bq   = (const float*)d_in[5];
    const float* Wk   = (const float*)d_in[6];
    const float* bk   = (const float*)d_in[7];
    const float* Wv   = (const float*)d_in[8];
    const float* bv   = (const float*)d_in[9];
    float* out = (float*)d_out;

    dim3 pgrid(B * S / PTM, 12);   // 50 x 12 = 600 blocks, 128 threads, one wave
    proj_tc_kernel<<<pgrid, 128>>>(x, Wq, bq, Wk, bk, Wv, bv);

    fused_attn_kernel<<<B * S, 128>>>(tK, tV, mask, out);
}

// round 11
// speedup vs baseline: 1.0350x; 1.0350x over previous
#include <cuda_runtime.h>
#include <cuda_bf16.h>
#include <cstdint>

#define B 16
#define S 200
#define D 256
#define H 8
#define W 32
#define RS 0.17677669529663689f   // 1/sqrt(32)

// ---------------- scratch (no allocations allowed) ----------------
__device__ float g_q[B * S * D];
__device__ float g_k[B * S * D];
__device__ float g_v[B * S * D];

// ---------------- tf32 helpers ----------------
__device__ __forceinline__ uint32_t tf32_hi_bits(float a) {
    return __float_as_uint(a) & 0xffffe000u;
}

__device__ __forceinline__ void mma_tf32(
    float& c0, float& c1, float& c2, float& c3,
    uint32_t a0, uint32_t a1, uint32_t a2, uint32_t a3,
    uint32_t b0, uint32_t b1)
{
    asm volatile(
        "mma.sync.aligned.m16n8k8.row.col.f32.tf32.tf32.f32 "
        "{%0,%1,%2,%3}, {%4,%5,%6,%7}, {%8,%9}, {%0,%1,%2,%3};"
        : "+f"(c0), "+f"(c1), "+f"(c2), "+f"(c3)
        : "r"(a0), "r"(a1), "r"(a2), "r"(a3), "r"(b0), "r"(b1));
}

// ---------------- cp.async helpers (proj only) ----------------
__device__ __forceinline__ void cp_async16(uint32_t dst, const void* src) {
    asm volatile("cp.async.cg.shared.global [%0], [%1], 16;" :: "r"(dst), "l"(src));
}
#define CP_COMMIT() asm volatile("cp.async.commit_group;" ::: "memory")
#define CP_WAIT1()  asm volatile("cp.async.wait_group 1;" ::: "memory")

// ---------------- kernel 1: tf32 TC projection, 2-pass compensation ----------------
// 64x32 tile, 1200 blocks, 256 threads, cp.async double-buffered.
// C = Ah*Bh + Al*Bh  (A fully compensated; B's low bits dropped -> ~2e-4 rel err)
#define PTM 64
#define PTN 32
#define PTK 32
#define PPAD 4
#define PLD (PTK + PPAD)

__global__ __launch_bounds__(256) void proj_tc_kernel(
    const float* __restrict__ x,
    const float* __restrict__ Wq, const float* __restrict__ bq,
    const float* __restrict__ Wk, const float* __restrict__ bk,
    const float* __restrict__ Wv, const float* __restrict__ bv)
{
    __shared__ float sa[2][PTM][PLD];   // x tiles
    __shared__ float sb[2][PTN][PLD];   // W tiles

    const int tid  = threadIdx.x;
    const int lane = tid & 31;
    const int wid  = tid >> 5;
    const int m0   = blockIdx.x * PTM;
    const int mat  = blockIdx.y >> 3;             // 0=q,1=k,2=v
    const int nc0  = (blockIdx.y & 7) * PTN;      // col block within matrix

    const float* Wm   = (mat == 0) ? Wq : (mat == 1) ? Wk : Wv;
    const float* bias = (mat == 0) ? bq : (mat == 1) ? bk : bv;
    float* dst        = (mat == 0) ? g_q : (mat == 1) ? g_k : g_v;

    const int warp_m = wid & 3;      // 4 warps over M (16 rows each)
    const int warp_n = wid >> 2;     // 2 warps over N (16 cols each)
    const int wm0 = warp_m * 16;
    const int wn0 = warp_n * 16;

    const int g  = lane >> 2;
    const int tg = lane & 3;

    // load mappings
    const int xrow = tid >> 2;           // 0..63, 8 floats each
    const int xk   = (tid & 3) * 8;
    const int wrow = tid >> 3;           // 0..31, 4 floats each
    const int wk   = (tid & 7) * 4;

    const float* xsrc = x  + (size_t)(m0  + xrow) * D + xk;
    const float* wsrc = Wm + (size_t)(nc0 + wrow) * D + wk;
    uint32_t sa_dst = (uint32_t)__cvta_generic_to_shared(&sa[0][xrow][xk]);
    uint32_t sb_dst = (uint32_t)__cvta_generic_to_shared(&sb[0][wrow][wk]);
    const uint32_t sa_str = (uint32_t)(PTM * PLD * 4);
    const uint32_t sb_str = (uint32_t)(PTN * PLD * 4);

    #define PROJ_PREFETCH(t, s)                                            \
        do {                                                               \
            cp_async16(sa_dst + (s) * sa_str,      xsrc + (t) * PTK);      \
            cp_async16(sa_dst + (s) * sa_str + 16, xsrc + (t) * PTK + 4);  \
            cp_async16(sb_dst + (s) * sb_str,      wsrc + (t) * PTK);      \
            CP_COMMIT();                                                   \
        } while (0)

    float c[2][4];
    #pragma unroll
    for (int j = 0; j < 2; j++)
        #pragma unroll
        for (int r = 0; r < 4; r++) c[j][r] = 0.f;

    PROJ_PREFETCH(0, 0);

    #pragma unroll 1
    for (int t = 0; t < D / PTK; t++) {
        if (t + 1 < D / PTK) PROJ_PREFETCH(t + 1, (t + 1) & 1);
        else                 CP_COMMIT();           // keep wait_group count aligned
        CP_WAIT1();
        __syncthreads();

        const int s = t & 1;
        #pragma unroll
        for (int kk = 0; kk < 4; kk++) {
            const int kc = kk * 8;
            float af[4];
            {
                const int rb = wm0 + g;
                af[0] = sa[s][rb    ][kc + tg];
                af[1] = sa[s][rb + 8][kc + tg];
                af[2] = sa[s][rb    ][kc + tg + 4];
                af[3] = sa[s][rb + 8][kc + tg + 4];
            }
            uint32_t bh[2][2];
            #pragma unroll
            for (int j = 0; j < 2; j++) {
                const int cb = wn0 + 8 * j + g;
                bh[j][0] = tf32_hi_bits(sb[s][cb][kc + tg]);
                bh[j][1] = tf32_hi_bits(sb[s][cb][kc + tg + 4]);
            }
            uint32_t ah[4], al[4];
            #pragma unroll
            for (int r = 0; r < 4; r++) {
                uint32_t hb = tf32_hi_bits(af[r]);
                ah[r] = hb;
                float lo = af[r] - __uint_as_float(hb);
                al[r] = tf32_hi_bits(lo);
            }
            #pragma unroll
            for (int j = 0; j < 2; j++) {
                mma_tf32(c[j][0], c[j][1], c[j][2], c[j][3],
                         ah[0], ah[1], ah[2], ah[3], bh[j][0], bh[j][1]);
                mma_tf32(c[j][0], c[j][1], c[j][2], c[j][3],
                         al[0], al[1], al[2], al[3], bh[j][0], bh[j][1]);
            }
        }
        __syncthreads();
    }

    const int r0 = m0 + wm0 + g;
    #pragma unroll
    for (int j = 0; j < 2; j++) {
        const int cg = nc0 + wn0 + 8 * j + tg * 2;
        const float b0v = bias[cg], b1v = bias[cg + 1];
        float2 v0 = make_float2(c[j][0] + b0v, c[j][1] + b1v);
        float2 v1 = make_float2(c[j][2] + b0v, c[j][3] + b1v);
        *(float2*)&dst[(size_t)r0 * D + cg]       = v0;
        *(float2*)&dst[(size_t)(r0 + 8) * D + cg] = v1;
    }
}

// ---------------- kernel 2: fused attention, 128 threads/block (frozen best) ----------------
__global__ __launch_bounds__(128, 12) void fused_attn_kernel(
    const float* __restrict__ tK, const float* __restrict__ tV,
    const int* __restrict__ mask, float* __restrict__ out)
{
    __shared__ float sp[H][S];          // 6.4 KB
    __shared__ float4 pbuf[2][64];      // 2 KB

    const int bi = blockIdx.x;
    const int b  = bi / S;
    const int warp = threadIdx.x >> 5;  // 0..3
    const int lane = threadIdx.x & 31;

    // ---- Phase A ----
    {
        const float* qrow = g_q + (size_t)bi * D + lane * 8;
        const float4 qa = *(const float4*)(qrow);
        const float4 qb = *(const float4*)(qrow + 4);

        #pragma unroll 5
        for (int j = warp; j < S; j += 4) {
            const float* tp = tK  + ((size_t)bi * S + j) * D + lane * 8;
            const float* kp = g_k + ((size_t)(b * S + j)) * D + lane * 8;
            float4 t0 = __ldcs((const float4*)(tp));
            float4 t1 = __ldcs((const float4*)(tp + 4));
            float4 k0 = *(const float4*)(kp);
            float4 k1 = *(const float4*)(kp + 4);

            float p = qa.x * (t0.x + k0.x) + qa.y * (t0.y + k0.y)
                    + qa.z * (t0.z + k0.z) + qa.w * (t0.w + k0.w)
                    + qb.x * (t1.x + k1.x) + qb.y * (t1.y + k1.y)
                    + qb.z * (t1.z + k1.z) + qb.w * (t1.w + k1.w);

            p += __shfl_xor_sync(0xFFFFFFFFu, p, 1);
            p += __shfl_xor_sync(0xFFFFFFFFu, p, 2);
            if ((lane & 3) == 0) sp[lane >> 2][j] = p;
        }
    }
    __syncthreads();

    // ---- Phase B: warp handles heads warp and warp+4 ----
    #pragma unroll
    for (int hh = 0; hh < 2; hh++) {
        const int h = warp + hh * 4;
        float vals[7];
        float mx = -1e30f;
        #pragma unroll
        for (int t = 0; t < 7; t++) {
            int j = lane + t * 32;
            if (j < S) {
                float mb = 10000.0f * (1.0f - (float)mask[b * S + j]);
                vals[t] = sp[h][j] * RS + mb;
            } else {
                vals[t] = -1e30f;
            }
            mx = fmaxf(mx, vals[t]);
        }
        #pragma unroll
        for (int o = 16; o; o >>= 1) mx = fmaxf(mx, __shfl_xor_sync(0xFFFFFFFFu, mx, o));

        float sum = 0.f;
        #pragma unroll
        for (int t = 0; t < 7; t++) {
            vals[t] = __expf(vals[t] - mx);
            sum += vals[t];
        }
        #pragma unroll
        for (int o = 16; o; o >>= 1) sum += __shfl_xor_sync(0xFFFFFFFFu, sum, o);

        const float inv = 1.0f / sum;
        #pragma unroll
        for (int t = 0; t < 7; t++) {
            int j = lane + t * 32;
            if (j < S) sp[h][j] = vals[t] * inv;
        }
    }
    __syncthreads();

    // ---- Phase C ----
    {
        const int g = threadIdx.x >> 6;     // j-group 0..1
        const int l = threadIdx.x & 63;     // d-slice 0..63
        const int d = l * 4;
        const int h = l >> 3;

        const float* tvb = tV  + ((size_t)bi * S) * D + d;
        const float* vvb = g_v + ((size_t)b * S) * D + d;

        float4 acc = make_float4(0.f, 0.f, 0.f, 0.f);
        #pragma unroll 5
        for (int j = g; j < S; j += 2) {
            float4 tv = __ldcs((const float4*)(tvb + (size_t)j * D));
            float4 vv = *(const float4*)(vvb + (size_t)j * D);
            float pj = sp[h][j];
            acc.x += pj * (tv.x + vv.x);
            acc.y += pj * (tv.y + vv.y);
            acc.z += pj * (tv.z + vv.z);
            acc.w += pj * (tv.w + vv.w);
        }
        pbuf[g][l] = acc;
    }
    __syncthreads();

    if (threadIdx.x < 64) {
        const int l = threadIdx.x;
        float4 a0 = pbuf[0][l], a1 = pbuf[1][l];
        float4 r;
        r.x = a0.x + a1.x;
        r.y = a0.y + a1.y;
        r.z = a0.z + a1.z;
        r.w = a0.w + a1.w;
        *(float4*)(out + (size_t)bi * D + l * 4) = r;
    }
}

// ---------------- launch ----------------
extern "C" void kernel_launch(void* const* d_in, const int* in_sizes, int n_in,
                              void* d_out, int out_size)
{
    const float* x    = (const float*)d_in[0];
    const float* tK   = (const float*)d_in[1];
    const float* tV   = (const float*)d_in[2];
    const int*   mask = (const int*)  d_in[3];
    const float* Wq   = (const float*)d_in[4];
    const float* bq   = (const float*)d_in[5];
    const float* Wk   = (const float*)d_in[6];
    const float* bk   = (const float*)d_in[7];
    const float* Wv   = (const float*)d_in[8];
    const float* bv   = (const float*)d_in[9];
    float* out = (float*)d_out;

    dim3 pgrid(B * S / PTM, 24);   // 50 x (3 matrices * 8 col blocks) = 1200 blocks
    proj_tc_kernel<<<pgrid, 256>>>(x, Wq, bq, Wk, bk, Wv, bv);

    fused_attn_kernel<<<B * S, 128>>>(tK, tV, mask, out);
}